// round 17
// baseline (speedup 1.0000x reference)
#include <cuda_runtime.h>
#include <cuda_fp16.h>
#include <math.h>

#define NUM_SPH 7
#define NUM_RAD 6
#define NBASIS  (NUM_SPH * NUM_RAD)   // 42
#define MAX_E   524288

#define TABN    512                   // lerp intervals over x in [0.1, 1.0]
#define NRECROW 32                    // padded row: 32 records = 256B (2 lines)

#define BT      128                   // triplets per out-block
#define OTPB    224                   // 7 warps; 128*42/2 = 2688 = 12*224
// single out launch (no chunking)

// root scan grid: x in [3.0, 3.0 + 0.02*1551 = 34.02]
#define SCAN_NP   1552
#define SCAN_LO   3.0f
#define SCAN_H    0.02f

// --------------------------------------------------------------------------
__device__ float g_zeros[NUM_SPH][NUM_RAD];
__device__ float g_norms[NUM_SPH][NUM_RAD];
// packed record per (row i, even j): half4 = (v_j, v_j+1, d_j, d_j+1), 8B.
// rows padded to 32 records = 256B (two aligned 128B lines). 131KB total.
__device__ __align__(256) uint2 g_tabp[(size_t)(TABN + 1) * NRECROW];

// --------------------------------------------------------------------------
// spherical Bessel pair (j_l, j_{l-1}): fp32 (scan/Newton) + fp64 (polish)
// --------------------------------------------------------------------------
__device__ __forceinline__ void jn_pair_f(int l, float z, float& f, float& fm) {
    float s, c;
    sincosf(z, &s, &c);
    float j0 = s / z;
    if (l == 0) { f = j0; fm = c / z; return; }      // j_{-1} = cos/z
    float j1 = s / (z * z) - c / z;
    float a = j0, b = j1;
    for (int i = 1; i < l; ++i) {
        float nx = (2.0f * i + 1.0f) / z * b - a;
        a = b; b = nx;
    }
    f = b; fm = a;
}

__device__ __forceinline__ void jn_pair_d(int l, double z, double& f, double& fm) {
    double s = sin(z), c = cos(z);
    double j0 = s / z;
    if (l == 0) { f = j0; fm = c / z; return; }
    double j1 = s / (z * z) - c / z;
    double a = j0, b = j1;
    for (int i = 1; i < l; ++i) {
        double nx = (2.0 * i + 1.0) / z * b - a;
        a = b; b = nx;
    }
    f = b; fm = a;
}

// --------------------------------------------------------------------------
// 1) roots: one block per l. fp32 scan -> brackets -> 5 fp32 Newton iters
//    -> ONE fp64 polish + fp64 norm (parallel across 42 threads total).
// --------------------------------------------------------------------------
__global__ void roots_kernel() {
    __shared__ unsigned char sg[SCAN_NP];
    __shared__ int cnt[256];
    __shared__ int brk[NUM_RAD];
    int l = blockIdx.x;
    int t = threadIdx.x;

    // ---- A: sign scan ----
    for (int p = t; p < SCAN_NP; p += 256) {
        float x = SCAN_LO + SCAN_H * (float)p;
        float v, vm;
        jn_pair_f(l, x, v, vm);
        sg[p] = (unsigned char)(v < 0.0f);
    }
    __syncthreads();

    // ---- B: brackets ----
    const int NI  = SCAN_NP - 1;
    const int per = (NI + 255) / 256;
    int i0 = t * per, i1 = i0 + per; if (i1 > NI) i1 = NI;

    int local = 0;
    for (int i = i0; i < i1; ++i) local += (sg[i] != sg[i + 1]);
    cnt[t] = local;
    __syncthreads();

    if (t == 0) {
        int run = 0;
        for (int j = 0; j < 256; ++j) { int c0 = cnt[j]; cnt[j] = run; run += c0; }
    }
    __syncthreads();

    int r = cnt[t];
    for (int i = i0; i < i1; ++i) {
        if (sg[i] != sg[i + 1]) {
            if (r < NUM_RAD) brk[r] = i;
            ++r;
        }
    }
    __syncthreads();

    // ---- C: Newton (fp32) + fp64 polish ----
    if (t < NUM_RAD) {
        int k = t;
        int i = brk[k];
        float lo = SCAN_LO + SCAN_H * (float)i - SCAN_H;   // expanded bracket
        float hi = lo + 3.0f * SCAN_H;
        float flo, fd;
        jn_pair_f(l, lo, flo, fd);

        float z = 0.5f * (lo + hi);
        #pragma unroll
        for (int it = 0; it < 5; ++it) {
            float f, fm;
            jn_pair_f(l, z, f, fm);
            if ((f < 0.0f) == (flo < 0.0f)) { lo = z; flo = f; } else { hi = z; }
            float fp = fm - ((float)(l + 1) / z) * f;
            float zn = z - f / fp;
            if (!(zn > lo && zn < hi)) zn = 0.5f * (lo + hi);
            z = zn;
        }

        // one fp64 Newton polish: fp32 root (~1e-6) -> ~1e-12
        double zd = (double)z;
        {
            double f, fm;
            jn_pair_d(l, zd, f, fm);
            double fp = fm - ((double)(l + 1) / zd) * f;
            zd = zd - f / fp;
        }

        double f7, fm7;
        jn_pair_d(l + 1, zd, f7, fm7);
        g_zeros[l][k] = (float)zd;
        g_norms[l][k] = (float)(sqrt(2.0) / fabs(f7));
    }
}

// --------------------------------------------------------------------------
// helper: fp32 reference recurrence, 6 radial values for (x, l)
// --------------------------------------------------------------------------
__device__ __forceinline__ void rbf_row(float x, int l,
                                        const float* zr, const float* nr,
                                        float* outv) {
    #pragma unroll
    for (int k = 0; k < NUM_RAD; ++k) {
        float z = x * zr[k];
        float s, c;
        sincosf(z, &s, &c);
        float j0 = s / z;
        float res = j0;
        if (l > 0) {
            float j1 = s / (z * z) - c / z;
            float jm = j0, jc = j1;
            for (int i = 1; i < l; ++i) {
                float jn = (2.0f * i + 1.0f) / z * jc - jm;
                jm = jc; jc = jn;
            }
            res = jc;
        }
        outv[k] = nr[k] * res;
    }
}

// --------------------------------------------------------------------------
// 2) Table-gen (point-parallel): one thread per (p, l); rbf at x_p and
//    x_{p+1}; packs (v, d) half4 records into the padded row.
// --------------------------------------------------------------------------
__global__ void tab_kernel() {
    int gid = blockIdx.x * blockDim.x + threadIdx.x;
    if (gid >= (TABN + 1) * NUM_SPH) return;
    int l = gid % NUM_SPH;
    int p = gid / NUM_SPH;
    float x0 = 0.1f + (0.9f / TABN) * (float)p;
    float x1 = 0.1f + (0.9f / TABN) * (float)(p + 1);   // d unused for p==TABN

    float zr[NUM_RAD], nr[NUM_RAD];
    #pragma unroll
    for (int k = 0; k < NUM_RAD; ++k) { zr[k] = g_zeros[l][k]; nr[k] = g_norms[l][k]; }

    float v0[NUM_RAD], v1[NUM_RAD];
    rbf_row(x0, l, zr, nr, v0);
    rbf_row(x1, l, zr, nr, v1);

    uint2* row = g_tabp + ((size_t)p << 5) + l * (NUM_RAD / 2);
    #pragma unroll
    for (int r = 0; r < NUM_RAD / 2; ++r) {
        __half2 vh = __floats2half2_rn(v0[2*r], v0[2*r+1]);
        __half2 dh = __floats2half2_rn(v1[2*r] - v0[2*r], v1[2*r+1] - v0[2*r+1]);
        uint2 rec;
        rec.x = *reinterpret_cast<unsigned*>(&vh);
        rec.y = *reinterpret_cast<unsigned*>(&dh);
        row[r] = rec;
    }
}

// --------------------------------------------------------------------------
// 3) FUSED out (best measured float2 structure): per float2 output =
//    1 scattered LDG.64 (packed record, L1-resident 131KB aligned table)
//    + LDS + dense STG.64 (evict-first).
// --------------------------------------------------------------------------
__global__ void __launch_bounds__(OTPB) out_kernel(
        const float* __restrict__ dist,
        const float* __restrict__ angle,
        const int*   __restrict__ idx_kj,
        float*       __restrict__ out) {
    __shared__ float scbf[BT][8];
    __shared__ float2 sif[BT];          // (row record-offset as int bits, lerp f)

    const float pref[NUM_SPH] = {
        0.28209479177387814f, 0.48860251190291992f, 0.63078313050504009f,
        0.74635266518023080f, 0.84628437532163443f, 0.93560257962738880f,
        1.01710723628205460f
    };

    int blk = blockIdx.x;
    int tid = threadIdx.x;
    int t0  = blk * BT;

    // ---- 1a ----
    if (tid < BT) {
        int t = t0 + tid;
        int e = __ldg(&idx_kj[t]);
        float x = __ldg(&dist[e]) * 0.2f;
        float u = (x - 0.1f) * ((float)TABN / 0.9f);
        if (u < 0.0f) u = 0.0f;
        int i = (int)u;
        if (i > TABN - 1) i = TABN - 1;
        sif[tid] = make_float2(__int_as_float(i << 5), u - (float)i);

        float ct = cosf(angle[t]);
        float pm = 1.0f, pc = ct;
        scbf[tid][0] = pref[0] * pm;
        scbf[tid][1] = pref[1] * pc;
        #pragma unroll
        for (int l = 2; l < NUM_SPH; ++l) {
            float pn = ((2.0f * l - 1.0f) * ct * pc - (l - 1.0f) * pm) / (float)l;
            pm = pc; pc = pn;
            scbf[tid][l] = pref[l] * pn;
        }
    }
    __syncthreads();

    // ---- 2 ----
    float2* o2 = reinterpret_cast<float2*>(out + (size_t)blk * (BT * NBASIS));

    #pragma unroll
    for (int it = 0; it < 12; ++it) {
        unsigned w  = it * OTPB + tid;          // 0..2687
        unsigned g  = 2u * w;                   // even
        unsigned tl = (g * 6242u) >> 18;        // g/42, exact for g<5376
        unsigned j  = g - tl * 42u;             // even, 0..40
        unsigned rj = j >> 1;                   // record index within row

        float2 rf = sif[tl];
        int    ro = __float_as_int(rf.x);       // i * 32
        float  f  = rf.y;

        uint2 rec = __ldg(&g_tabp[ro + rj]);
        float2 v = __half22float2(*reinterpret_cast<__half2*>(&rec.x));
        float2 d = __half22float2(*reinterpret_cast<__half2*>(&rec.y));

        float c = scbf[tl][(j * 171u) >> 10];   // j/6

        float2 r;
        r.x = (v.x + f * d.x) * c;
        r.y = (v.y + f * d.y) * c;
        __stcs(&o2[w], r);
    }
}

// --------------------------------------------------------------------------
extern "C" void kernel_launch(void* const* d_in, const int* in_sizes, int n_in,
                              void* d_out, int out_size) {
    const float* dist  = (const float*)d_in[0];
    const float* angle = (const float*)d_in[1];
    const int*   idx   = (const int*)  d_in[2];
    float*       out   = (float*)      d_out;
    int T = in_sizes[1];

    roots_kernel<<<NUM_SPH, 256>>>();

    int nTab = (TABN + 1) * NUM_SPH;
    tab_kernel<<<(nTab + 255) / 256, 256>>>();

    out_kernel<<<T / BT, OTPB>>>(dist, angle, idx, out);
}